// round 1
// baseline (speedup 1.0000x reference)
#include <cuda_runtime.h>
#include <cuda_bf16.h>
#include <cstdint>

// soft_to_hard_quantize: N vectors of D=16 floats, M=64 codewords of 16 floats.
// logit_m = (10*dot(x,r_m) - 5*||r_m||^2) * log2(e)   (||x||^2 cancels in softmax)
// z = sum_m exp2(logit_m - max) * r_m / sum_m exp2(logit_m - max)

#define MCODE 64
#define DVEC  16
#define TPB   256

typedef unsigned long long u64;

__device__ __forceinline__ u64 fma2(u64 a, u64 b, u64 c) {
    u64 d;
    asm("fma.rn.f32x2 %0, %1, %2, %3;" : "=l"(d) : "l"(a), "l"(b), "l"(c));
    return d;
}
__device__ __forceinline__ u64 mul2(u64 a, u64 b) {
    u64 d;
    asm("mul.rn.f32x2 %0, %1, %2;" : "=l"(d) : "l"(a), "l"(b));
    return d;
}
__device__ __forceinline__ u64 pack2(float lo, float hi) {
    u64 r;
    asm("mov.b64 %0, {%1, %2};" : "=l"(r) : "f"(lo), "f"(hi));
    return r;
}
__device__ __forceinline__ void unpack2(u64 v, float& lo, float& hi) {
    asm("mov.b64 {%0, %1}, %2;" : "=f"(lo), "=f"(hi) : "l"(v));
}
__device__ __forceinline__ float ex2f(float x) {
    float r;
    asm("ex2.approx.ftz.f32 %0, %1;" : "=f"(r) : "f"(x));
    return r;
}

__global__ __launch_bounds__(TPB)
void stq_kernel(const float* __restrict__ x,
                const float* __restrict__ ref,
                float* __restrict__ out,
                int nvec) {
    // Codebook staged in shared memory as packed f32 pairs: rp[m*8 + p] holds
    // (r_m[2p], r_m[2p+1]). b2[m] = -5*log2(e)*||r_m||^2.
    __shared__ u64  rp[MCODE * 8];
    __shared__ float b2[MCODE];

    const int tid = threadIdx.x;

    // 1024 ref floats = 256 x 16B. Harness buffers are >=16B aligned.
    if (tid < 256) {
        ulonglong2 q = reinterpret_cast<const ulonglong2*>(ref)[tid];
        rp[2 * tid + 0] = q.x;
        rp[2 * tid + 1] = q.y;
    }
    if (tid < MCODE) {
        float s = 0.0f;
        #pragma unroll
        for (int i = 0; i < DVEC; i++) {
            float r = ref[tid * DVEC + i];
            s = fmaf(r, r, s);
        }
        // -5 * log2(e)
        b2[tid] = -7.2134752044448169f * s;
    }
    __syncthreads();

    const int v = blockIdx.x * TPB + tid;
    if (v >= nvec) return;

    // Load this thread's 16-float vector as 8 packed pairs (4 x 128-bit LDG).
    const ulonglong2* xin = reinterpret_cast<const ulonglong2*>(x + (size_t)v * DVEC);
    u64 xp[8];
    #pragma unroll
    for (int i = 0; i < 4; i++) {
        ulonglong2 t = xin[i];
        xp[2 * i + 0] = t.x;
        xp[2 * i + 1] = t.y;
    }

    // ---- Pass 1: logits (scaled by log2 e) ----
    float l[MCODE];
    const ulonglong2* rp2 = reinterpret_cast<const ulonglong2*>(rp);
    #pragma unroll 8
    for (int m = 0; m < MCODE; m++) {
        ulonglong2 q0 = rp2[m * 4 + 0];
        ulonglong2 q1 = rp2[m * 4 + 1];
        ulonglong2 q2 = rp2[m * 4 + 2];
        ulonglong2 q3 = rp2[m * 4 + 3];
        u64 acc = fma2(xp[0], q0.x, 0ULL);
        acc = fma2(xp[1], q0.y, acc);
        acc = fma2(xp[2], q1.x, acc);
        acc = fma2(xp[3], q1.y, acc);
        acc = fma2(xp[4], q2.x, acc);
        acc = fma2(xp[5], q2.y, acc);
        acc = fma2(xp[6], q3.x, acc);
        acc = fma2(xp[7], q3.y, acc);
        float lo, hi;
        unpack2(acc, lo, hi);
        // 10 * log2(e) = 14.4269504...
        l[m] = fmaf(14.426950408889634f, lo + hi, b2[m]);
    }

    // ---- max over logits (4 parallel chains) ----
    float m0 = l[0], m1 = l[1], m2 = l[2], m3 = l[3];
    #pragma unroll
    for (int m = 4; m < MCODE; m += 4) {
        m0 = fmaxf(m0, l[m + 0]);
        m1 = fmaxf(m1, l[m + 1]);
        m2 = fmaxf(m2, l[m + 2]);
        m3 = fmaxf(m3, l[m + 3]);
    }
    const float mx = fmaxf(fmaxf(m0, m1), fmaxf(m2, m3));

    // ---- Pass 2: exp + weighted codeword accumulation ----
    float s[4] = {0.0f, 0.0f, 0.0f, 0.0f};
    u64 zp[8];
    #pragma unroll
    for (int p = 0; p < 8; p++) zp[p] = 0ULL;

    #pragma unroll
    for (int m = 0; m < MCODE; m++) {
        float e = ex2f(l[m] - mx);
        s[m & 3] += e;
        u64 ee = pack2(e, e);
        ulonglong2 q0 = rp2[m * 4 + 0];
        ulonglong2 q1 = rp2[m * 4 + 1];
        ulonglong2 q2 = rp2[m * 4 + 2];
        ulonglong2 q3 = rp2[m * 4 + 3];
        zp[0] = fma2(ee, q0.x, zp[0]);
        zp[1] = fma2(ee, q0.y, zp[1]);
        zp[2] = fma2(ee, q1.x, zp[2]);
        zp[3] = fma2(ee, q1.y, zp[3]);
        zp[4] = fma2(ee, q2.x, zp[4]);
        zp[5] = fma2(ee, q2.y, zp[5]);
        zp[6] = fma2(ee, q3.x, zp[6]);
        zp[7] = fma2(ee, q3.y, zp[7]);
    }

    const float inv = 1.0f / ((s[0] + s[1]) + (s[2] + s[3]));
    const u64 iv = pack2(inv, inv);

    ulonglong2* o = reinterpret_cast<ulonglong2*>(out + (size_t)v * DVEC);
    #pragma unroll
    for (int i = 0; i < 4; i++) {
        ulonglong2 t;
        t.x = mul2(zp[2 * i + 0], iv);
        t.y = mul2(zp[2 * i + 1], iv);
        o[i] = t;
    }
}

extern "C" void kernel_launch(void* const* d_in, const int* in_sizes, int n_in,
                              void* d_out, int out_size) {
    const float* x   = (const float*)d_in[0];   // (64,8,32,32,16) f32
    const float* ref = (const float*)d_in[1];   // (64,16) f32
    float* out = (float*)d_out;                 // same shape as x

    const int nvec = in_sizes[0] / DVEC;        // 524288
    const int blocks = (nvec + TPB - 1) / TPB;
    stq_kernel<<<blocks, TPB>>>(x, ref, out, nvec);
}